// round 11
// baseline (speedup 1.0000x reference)
#include <cuda_runtime.h>
#include <cuda_bf16.h>
#include <stdint.h>
#include <math.h>

#define T_TOK 8192
#define DIM 1024
#define NEXP 16
#define INTER 2048
#define NROWS (2*T_TOK)

#define TM 64
#define TN 128
#define TKC 16
#define KW 12          // words per smem row (8 data + 4 pad) — bank-verified

// ---------------- device scratch (total ~402 MB, inside proven envelope) -------
__device__ int   g_cnt[NEXP];
__device__ int   g_rows[NEXP][T_TOK];   // value = 2*token + slot
__device__ float g_wt[NEXP][T_TOK];
__device__ __align__(16) uint32_t g_Hh[(size_t)NROWS * (INTER/2)];     // 67 MB
__device__ __align__(16) uint32_t g_Hl[(size_t)NROWS * (INTER/2)];     // 67 MB
__device__ __align__(16) uint32_t g_W1h[(size_t)NEXP*INTER*(DIM/2)];   // 67 MB
__device__ __align__(16) uint32_t g_W1l[(size_t)NEXP*INTER*(DIM/2)];
__device__ __align__(16) uint32_t g_W3h[(size_t)NEXP*INTER*(DIM/2)];
__device__ __align__(16) uint32_t g_W3l[(size_t)NEXP*INTER*(DIM/2)];

#define MMA16816(d, a, b0, b1) \
    asm volatile("mma.sync.aligned.m16n8k16.row.col.f32.bf16.bf16.f32 " \
        "{%0,%1,%2,%3}, {%4,%5,%6,%7}, {%8,%9}, {%0,%1,%2,%3};" \
        : "+f"((d)[0]), "+f"((d)[1]), "+f"((d)[2]), "+f"((d)[3]) \
        : "r"((a)[0]), "r"((a)[1]), "r"((a)[2]), "r"((a)[3]), "r"(b0), "r"(b1))

__device__ __forceinline__ void f2bf_pair(float v0, float v1,
                                          uint32_t& hi, uint32_t& lo) {
    uint32_t h;
    asm("cvt.rn.bf16x2.f32 %0, %1, %2;" : "=r"(h) : "f"(v1), "f"(v0));
    float h0 = __uint_as_float(h << 16);
    float h1 = __uint_as_float(h & 0xffff0000u);
    uint32_t l;
    asm("cvt.rn.bf16x2.f32 %0, %1, %2;" : "=r"(l) : "f"(v1 - h1), "f"(v0 - h0));
    hi = h; lo = l;
}

// ---------------- kernel 0: reset counters + zero output ----------------
__global__ void zero_kernel(float* __restrict__ y) {
    int i = blockIdx.x * blockDim.x + threadIdx.x;
    if (i < NEXP) g_cnt[i] = 0;
    if (i < T_TOK * DIM / 4) {
        float4 z = make_float4(0.f, 0.f, 0.f, 0.f);
        reinterpret_cast<float4*>(y)[i] = z;
    }
}

// ---------------- kernel 1: gate (unchanged, passing) ----------------
__global__ void gate_kernel(const float* __restrict__ x,
                            const float* __restrict__ Wg,
                            const float* __restrict__ bg) {
    int t = blockIdx.x;
    int tid = threadIdx.x;
    int e = tid & 15;
    int c = tid >> 4;
    __shared__ float part[8][17];
    __shared__ float sc[16];

    const float* xr = x + (size_t)t * DIM;
    const float* wc = Wg + e;
    float s = 0.f;
    int d0 = c * 128;
#pragma unroll 4
    for (int d = 0; d < 128; d++)
        s = fmaf(xr[d0 + d], wc[(size_t)(d0 + d) * NEXP], s);
    part[c][e] = s;
    __syncthreads();

    if (tid < 16) {
        float v = bg[tid];
#pragma unroll
        for (int cc = 0; cc < 8; cc++) v += part[cc][tid];
        sc[tid] = v;
    }
    __syncthreads();

    if (tid == 0) {
        int i1 = 0; float v1 = sc[0];
#pragma unroll
        for (int j = 1; j < 16; j++) if (sc[j] > v1) { v1 = sc[j]; i1 = j; }
        int i2 = -1; float v2 = -3.0e38f;
#pragma unroll
        for (int j = 0; j < 16; j++) if (j != i1 && sc[j] > v2) { v2 = sc[j]; i2 = j; }
        float r  = expf(v2 - v1);
        float w1 = 1.f / (1.f + r);
        float w2 = r   / (1.f + r);
        int p1 = atomicAdd(&g_cnt[i1], 1);
        g_rows[i1][p1] = 2 * t;     g_wt[i1][p1] = w1;
        int p2 = atomicAdd(&g_cnt[i2], 1);
        g_rows[i2][p2] = 2 * t + 1; g_wt[i2][p2] = w2;
    }
}

// ---------------- kernel: weight transpose + split + pack ----------------
// W: [E][Kd][Nd] fp32 -> Whi/Wlo: [E][Nd][Kd/2] packed bf16 pairs (k in low half)
__global__ void wsplit_kernel(const float* __restrict__ W,
                              uint32_t* __restrict__ Whi,
                              uint32_t* __restrict__ Wlo,
                              int Kd, int Nd) {
    __shared__ float t[32][33];
    int e  = blockIdx.z;
    int n0 = blockIdx.x * 32;
    int k0 = blockIdx.y * 32;
    int tx = threadIdx.x, ty = threadIdx.y;       // (32, 8)
    const float* Wb = W + (size_t)e * Kd * Nd;
#pragma unroll
    for (int r = ty; r < 32; r += 8)
        t[r][tx] = Wb[(size_t)(k0 + r) * Nd + n0 + tx];
    __syncthreads();

    int tid = ty * 32 + tx;
    int kpl = tid & 15;        // kpair within tile (0..15)
    int nl  = tid >> 4;        // 0..15
    size_t rowstride = (size_t)(Kd / 2);
#pragma unroll
    for (int nn = nl; nn < 32; nn += 16) {
        float v0 = t[2 * kpl][nn];
        float v1 = t[2 * kpl + 1][nn];
        uint32_t h, l;
        f2bf_pair(v0, v1, h, l);
        size_t o = ((size_t)e * Nd + n0 + nn) * rowstride + (k0 / 2) + kpl;
        Whi[o] = h;
        Wlo[o] = l;
    }
}

// =======================================================================
// up kernel (fused W1/W3): h = silu(xW1+b1)*(xW3+b3) -> packed Hh/Hl
// TM=64, TN=128, TKC=16, single-buffer, preconverted B (pure copy stage)
// =======================================================================
__global__ __launch_bounds__(256, 2)
void up_kernel(const float* __restrict__ x,
               const float* __restrict__ b1, const float* __restrict__ b3) {
    int e = blockIdx.z;
    int cnt = g_cnt[e];
    int m0 = blockIdx.y * TM;
    if (m0 >= cnt) return;
    int n0 = blockIdx.x * TN;

    __shared__ __align__(16) uint32_t sAh[TM*KW],  sAl[TM*KW];
    __shared__ __align__(16) uint32_t sB1h[TN*KW], sB1l[TN*KW];
    __shared__ __align__(16) uint32_t sB3h[TN*KW], sB3l[TN*KW];
    __shared__ int sTokRow[TM];
    __shared__ int sOutRow[TM];

    int tid = threadIdx.x;
    int wid = tid >> 5;
    int lane = tid & 31;
    int grp = lane >> 2;
    int tig = lane & 3;
    int wm = (wid >> 2) * 32;
    int wn = (wid & 3) * 32;

    if (tid < TM) {
        int m = m0 + tid;
        if (m < cnt) { int r = g_rows[e][m]; sTokRow[tid] = r >> 1; sOutRow[tid] = r; }
        else         { sTokRow[tid] = -1;    sOutRow[tid] = -1; }
    }
    __syncthreads();

    // A loader: row = tid>>2 (0..63), q = tid&3 -> float4 of x
    int arow = tid >> 2, aq = tid & 3;
    int myTok = sTokRow[arow];
    const float* aptr = (myTok >= 0) ? (x + (size_t)myTok * DIM + aq * 4) : x;
    // B loader: bn = tid>>1 (0..127), bq = tid&1 -> one uint4 per array
    int bn = tid >> 1, bq = tid & 1;
    size_t brow = ((size_t)e * INTER + n0 + bn) * (DIM / 2);
    const uint4* p1h = reinterpret_cast<const uint4*>(g_W1h + brow);
    const uint4* p1l = reinterpret_cast<const uint4*>(g_W1l + brow);
    const uint4* p3h = reinterpret_cast<const uint4*>(g_W3h + brow);
    const uint4* p3l = reinterpret_cast<const uint4*>(g_W3l + brow);

    float4 rA;
    uint4 r1h, r1l, r3h, r3l;
    const float4 zf4 = make_float4(0.f, 0.f, 0.f, 0.f);

    auto fetch = [&](int c) {
        rA = (myTok >= 0) ? *reinterpret_cast<const float4*>(aptr + c * TKC) : zf4;
        int ui = c * 2 + bq;        // uint4 index within row: (c*8 + bq*4)/4
        r1h = p1h[ui]; r1l = p1l[ui];
        r3h = p3h[ui]; r3l = p3l[ui];
    };
    auto stage = [&]() {
        uint32_t h0, l0, h1, l1;
        f2bf_pair(rA.x, rA.y, h0, l0);
        f2bf_pair(rA.z, rA.w, h1, l1);
        int ab = arow * KW + aq * 2;
        *reinterpret_cast<uint2*>(&sAh[ab]) = make_uint2(h0, h1);
        *reinterpret_cast<uint2*>(&sAl[ab]) = make_uint2(l0, l1);
        int bb = bn * KW + bq * 4;
        *reinterpret_cast<uint4*>(&sB1h[bb]) = r1h;
        *reinterpret_cast<uint4*>(&sB1l[bb]) = r1l;
        *reinterpret_cast<uint4*>(&sB3h[bb]) = r3h;
        *reinterpret_cast<uint4*>(&sB3l[bb]) = r3l;
    };

    float acc1[2][4][4], acc3[2][4][4];
#pragma unroll
    for (int mt = 0; mt < 2; mt++)
#pragma unroll
        for (int nt = 0; nt < 4; nt++)
#pragma unroll
            for (int j = 0; j < 4; j++) { acc1[mt][nt][j] = 0.f; acc3[mt][nt][j] = 0.f; }

    const int NC = DIM / TKC;   // 64
    fetch(0);
    for (int c = 0; c < NC; c++) {
        stage();
        __syncthreads();
        if (c + 1 < NC) fetch(c + 1);   // overlap LDG with MMA

        uint32_t ah[2][4], al[2][4];
#pragma unroll
        for (int mt = 0; mt < 2; mt++) {
            int r0 = (wm + mt * 16 + grp) * KW;
            int r1 = r0 + 8 * KW;
            ah[mt][0] = sAh[r0 + tig];     ah[mt][1] = sAh[r1 + tig];
            ah[mt][2] = sAh[r0 + tig + 4]; ah[mt][3] = sAh[r1 + tig + 4];
            al[mt][0] = sAl[r0 + tig];     al[mt][1] = sAl[r1 + tig];
            al[mt][2] = sAl[r0 + tig + 4]; al[mt][3] = sAl[r1 + tig + 4];
        }
#pragma unroll
        for (int nt = 0; nt < 4; nt++) {
            int nb = (wn + nt * 8 + grp) * KW;
            uint32_t b1h0 = sB1h[nb + tig], b1h1 = sB1h[nb + tig + 4];
            uint32_t b1l0 = sB1l[nb + tig], b1l1 = sB1l[nb + tig + 4];
            uint32_t b3h0 = sB3h[nb + tig], b3h1 = sB3h[nb + tig + 4];
            uint32_t b3l0 = sB3l[nb + tig], b3l1 = sB3l[nb + tig + 4];
#pragma unroll
            for (int mt = 0; mt < 2; mt++) {
                MMA16816(acc1[mt][nt], ah[mt], b1h0, b1h1);
                MMA16816(acc1[mt][nt], ah[mt], b1l0, b1l1);
                MMA16816(acc1[mt][nt], al[mt], b1h0, b1h1);
                MMA16816(acc3[mt][nt], ah[mt], b3h0, b3h1);
                MMA16816(acc3[mt][nt], ah[mt], b3l0, b3l1);
                MMA16816(acc3[mt][nt], al[mt], b3h0, b3h1);
            }
        }
        __syncthreads();
    }

    // epilogue: h = silu(z1+b1)*(z3+b3) -> packed split-bf16 H (R8-proven)
    const float* pb1 = b1 + (size_t)e * INTER + n0;
    const float* pb3 = b3 + (size_t)e * INTER + n0;
#pragma unroll
    for (int mt = 0; mt < 2; mt++) {
#pragma unroll
        for (int half = 0; half < 2; half++) {
            int rloc = wm + mt * 16 + grp + half * 8;
            int hr = sOutRow[rloc];
            if (hr < 0) continue;
#pragma unroll
            for (int nt = 0; nt < 4; nt++) {
                int col = wn + nt * 8 + tig * 2;
                float z1a = acc1[mt][nt][half * 2]     + pb1[col];
                float z1b = acc1[mt][nt][half * 2 + 1] + pb1[col + 1];
                float z3a = acc3[mt][nt][half * 2]     + pb3[col];
                float z3b = acc3[mt][nt][half * 2 + 1] + pb3[col + 1];
                float ha = (z1a / (1.f + expf(-z1a))) * z3a;
                float hb = (z1b / (1.f + expf(-z1b))) * z3b;
                uint32_t hp, lp;
                f2bf_pair(ha, hb, hp, lp);
                g_Hh[(size_t)hr * (INTER/2) + (n0 + col)/2] = hp;
                g_Hl[(size_t)hr * (INTER/2) + (n0 + col)/2] = lp;
            }
        }
    }
}

// =======================================================================
// down GEMM: y[tok] += w * (gather(H) @ W2 + b2)  — R10 verbatim (proven)
// =======================================================================
__global__ __launch_bounds__(256, 2)
void down_kernel(const float* __restrict__ W2, const float* __restrict__ b2,
                 float* __restrict__ y) {
    int e = blockIdx.z;
    int cnt = g_cnt[e];
    int m0 = blockIdx.y * TM;
    if (m0 >= cnt) return;
    int n0 = blockIdx.x * TN;

    __shared__ __align__(16) uint32_t sAh[2][TM*KW], sAl[2][TM*KW];
    __shared__ __align__(16) uint32_t sBh[2][TN*KW], sBl[2][TN*KW];
    __shared__ int   sHRow[TM];
    __shared__ int   sTok[TM];
    __shared__ float sW[TM];

    int tid = threadIdx.x;
    int wid = tid >> 5;
    int lane = tid & 31;
    int grp = lane >> 2;
    int tig = lane & 3;
    int wm = (wid >> 2) * 32;
    int wn = (wid & 3) * 32;

    if (tid < TM) {
        int m = m0 + tid;
        if (m < cnt) {
            int r = g_rows[e][m];
            sHRow[tid] = r; sTok[tid] = r >> 1; sW[tid] = g_wt[e][m];
        } else { sHRow[tid] = -1; sTok[tid] = -1; sW[tid] = 0.f; }
    }
    __syncthreads();

    const float* W2e = W2 + (size_t)e * INTER * DIM + n0;   // [k][n]

    int arow = tid >> 2, aq = tid & 3;
    int myH = sHRow[arow];
    const uint2* pAh = reinterpret_cast<const uint2*>(
        g_Hh + (size_t)(myH < 0 ? 0 : myH) * (INTER/2));
    const uint2* pAl = reinterpret_cast<const uint2*>(
        g_Hl + (size_t)(myH < 0 ? 0 : myH) * (INTER/2));
    int bn = tid & 127;
    int bkg = (tid >> 7) * 8;

    uint2 rAh, rAl;
    float rB[8];
    const uint2 zu2 = make_uint2(0, 0);

    auto fetch = [&](int k0) {    // k0 = element offset
        int ui = (k0 >> 2) + aq;  // uint2 index within row
        rAh = (myH >= 0) ? pAh[ui] : zu2;
        rAl = (myH >= 0) ? pAl[ui] : zu2;
#pragma unroll
        for (int j = 0; j < 8; j++)
            rB[j] = W2e[(size_t)(k0 + bkg + j) * DIM + bn];
    };
    auto stage = [&](int buf) {
        int ab = arow * KW + aq * 2;
        *reinterpret_cast<uint2*>(&sAh[buf][ab]) = rAh;
        *reinterpret_cast<uint2*>(&sAl[buf][ab]) = rAl;
        int bb = bn * KW + (bkg >> 1);
        uint32_t bh[4], bl[4];
#pragma unroll
        for (int j = 0; j < 4; j++) f2bf_pair(rB[2*j], rB[2*j+1], bh[j], bl[j]);
        *reinterpret_cast<uint4*>(&sBh[buf][bb]) = make_uint4(bh[0], bh[1], bh[2], bh[3]);
        *reinterpret_cast<uint4*>(&sBl[buf][bb]) = make_uint4(bl[0], bl[1], bl[2], bl[3]);
    };

    float acc[2][4][4];
#pragma unroll
    for (int mt = 0; mt < 2; mt++)
#pragma unroll
        for (int nt = 0; nt < 4; nt++)
#pragma unroll
            for (int j = 0; j < 4; j++) acc[mt][nt][j] = 0.f;

    const int NC = INTER / TKC;   // 128
    fetch(0); stage(0);
    __syncthreads();
    fetch(TKC);

    for (int c = 0; c < NC; c++) {
        int cb = c & 1;
        if (c + 1 < NC) stage((c + 1) & 1);
        if (c + 2 < NC) fetch((c + 2) * TKC);

        uint32_t ah[2][4], al[2][4];
#pragma unroll
        for (int mt = 0; mt < 2; mt++) {
            int r0 = (wm + mt * 16 + grp) * KW;
            int r1 = r0 + 8 * KW;
            ah[mt][0] = sAh[cb][r0 + tig];     ah[mt][1] = sAh[cb][r1 + tig];
            ah[mt][2] = sAh[cb][r0 + tig + 4]; ah[mt][3] = sAh[cb][r1 + tig + 4];
            al[mt][0] = sAl[cb][r0 + tig];     al[mt][1] = sAl[cb][r1 + tig];
            al[mt][2] = sAl[cb][r0 + tig + 4]; al[mt][3] = sAl[cb][r1 + tig + 4];
        }
#pragma unroll
        for (int nt = 0; nt < 4; nt++) {
            int nb = (wn + nt * 8 + grp) * KW;
            uint32_t bh0 = sBh[cb][nb + tig], bh1 = sBh[cb][nb + tig + 4];
            uint32_t bl0 = sBl[cb][nb + tig], bl1 = sBl[cb][nb + tig + 4];
#pragma unroll
            for (int mt = 0; mt < 2; mt++) {
                MMA16816(acc[mt][nt], ah[mt], bh0, bh1);
                MMA16816(acc[mt][nt], ah[mt], bl0, bl1);
                MMA16816(acc[mt][nt], al[mt], bh0, bh1);
            }
        }
        __syncthreads();
    }

    const float* pb2 = b2 + (size_t)e * DIM + n0;
#pragma unroll
    for (int mt = 0; mt < 2; mt++) {
#pragma unroll
        for (int half = 0; half < 2; half++) {
            int rloc = wm + mt * 16 + grp + half * 8;
            int tok = sTok[rloc];
            if (tok < 0) continue;
            float w = sW[rloc];
            float* yr = y + (size_t)tok * DIM + n0;
#pragma unroll
            for (int nt = 0; nt < 4; nt++) {
                int col = wn + nt * 8 + tig * 2;
                atomicAdd(yr + col,     (acc[mt][nt][half * 2]     + pb2[col])     * w);
                atomicAdd(yr + col + 1, (acc[mt][nt][half * 2 + 1] + pb2[col + 1]) * w);
            }
        }
    }
}

// -------------------------------- launcher --------------------------------------
extern "C" void kernel_launch(void* const* d_in, const int* in_sizes, int n_in,
                              void* d_out, int out_size) {
    const float* x  = (const float*)d_in[0];
    const float* Wg = (const float*)d_in[1];
    const float* bg = (const float*)d_in[2];
    const float* W1 = (const float*)d_in[3];
    const float* b1 = (const float*)d_in[4];
    const float* W2 = (const float*)d_in[5];
    const float* b2 = (const float*)d_in[6];
    const float* W3 = (const float*)d_in[7];
    const float* b3 = (const float*)d_in[8];
    float* y = (float*)d_out;

    zero_kernel<<<(T_TOK * DIM / 4 + 255) / 256, 256>>>(y);
    gate_kernel<<<T_TOK, 128>>>(x, Wg, bg);

    uint32_t* w1h; cudaGetSymbolAddress((void**)&w1h, g_W1h);
    uint32_t* w1l; cudaGetSymbolAddress((void**)&w1l, g_W1l);
    uint32_t* w3h; cudaGetSymbolAddress((void**)&w3h, g_W3h);
    uint32_t* w3l; cudaGetSymbolAddress((void**)&w3l, g_W3l);
    dim3 wsGrid(INTER / 32, DIM / 32, NEXP);
    wsplit_kernel<<<wsGrid, dim3(32, 8)>>>(W1, w1h, w1l, DIM, INTER);
    wsplit_kernel<<<wsGrid, dim3(32, 8)>>>(W3, w3h, w3l, DIM, INTER);

    dim3 upGrid(INTER / TN, T_TOK / TM, NEXP);
    up_kernel<<<upGrid, 256>>>(x, b1, b3);

    dim3 dnGrid(DIM / TN, T_TOK / TM, NEXP);
    down_kernel<<<dnGrid, 256>>>(W2, b2, y);
}

// round 12
// speedup vs baseline: 1.3628x; 1.3628x over previous
#include <cuda_runtime.h>
#include <cuda_bf16.h>
#include <stdint.h>
#include <math.h>

#define T_TOK 8192
#define DIM 1024
#define NEXP 16
#define INTER 2048
#define NROWS (2*T_TOK)

#define TKC 16
#define KW 12          // words per smem row (8 data + 4 pad) — bank-verified

// ---------------- device scratch (134 MB) ----------------
__device__ int   g_cnt[NEXP];
__device__ int   g_rows[NEXP][T_TOK];   // value = 2*token + slot
__device__ float g_wt[NEXP][T_TOK];
__device__ float g_H[(size_t)NROWS * INTER];   // fp32 intermediate

#define MMA16816(d, a, b0, b1) \
    asm volatile("mma.sync.aligned.m16n8k16.row.col.f32.bf16.bf16.f32 " \
        "{%0,%1,%2,%3}, {%4,%5,%6,%7}, {%8,%9}, {%0,%1,%2,%3};" \
        : "+f"((d)[0]), "+f"((d)[1]), "+f"((d)[2]), "+f"((d)[3]) \
        : "r"((a)[0]), "r"((a)[1]), "r"((a)[2]), "r"((a)[3]), "r"(b0), "r"(b1))

__device__ __forceinline__ void f2bf_pair(float v0, float v1,
                                          uint32_t& hi, uint32_t& lo) {
    uint32_t h;
    asm("cvt.rn.bf16x2.f32 %0, %1, %2;" : "=r"(h) : "f"(v1), "f"(v0));
    float h0 = __uint_as_float(h << 16);
    float h1 = __uint_as_float(h & 0xffff0000u);
    uint32_t l;
    asm("cvt.rn.bf16x2.f32 %0, %1, %2;" : "=r"(l) : "f"(v1 - h1), "f"(v0 - h0));
    hi = h; lo = l;
}

// ---------------- kernel 0: reset counters + zero output ----------------
__global__ void zero_kernel(float* __restrict__ y) {
    int i = blockIdx.x * blockDim.x + threadIdx.x;
    if (i < NEXP) g_cnt[i] = 0;
    if (i < T_TOK * DIM / 4) {
        float4 z = make_float4(0.f, 0.f, 0.f, 0.f);
        reinterpret_cast<float4*>(y)[i] = z;
    }
}

// ---------------- kernel 1: gate (unchanged, passing) ----------------
__global__ void gate_kernel(const float* __restrict__ x,
                            const float* __restrict__ Wg,
                            const float* __restrict__ bg) {
    int t = blockIdx.x;
    int tid = threadIdx.x;
    int e = tid & 15;
    int c = tid >> 4;
    __shared__ float part[8][17];
    __shared__ float sc[16];

    const float* xr = x + (size_t)t * DIM;
    const float* wc = Wg + e;
    float s = 0.f;
    int d0 = c * 128;
#pragma unroll 4
    for (int d = 0; d < 128; d++)
        s = fmaf(xr[d0 + d], wc[(size_t)(d0 + d) * NEXP], s);
    part[c][e] = s;
    __syncthreads();

    if (tid < 16) {
        float v = bg[tid];
#pragma unroll
        for (int cc = 0; cc < 8; cc++) v += part[cc][tid];
        sc[tid] = v;
    }
    __syncthreads();

    if (tid == 0) {
        int i1 = 0; float v1 = sc[0];
#pragma unroll
        for (int j = 1; j < 16; j++) if (sc[j] > v1) { v1 = sc[j]; i1 = j; }
        int i2 = -1; float v2 = -3.0e38f;
#pragma unroll
        for (int j = 0; j < 16; j++) if (j != i1 && sc[j] > v2) { v2 = sc[j]; i2 = j; }
        float r  = expf(v2 - v1);
        float w1 = 1.f / (1.f + r);
        float w2 = r   / (1.f + r);
        int p1 = atomicAdd(&g_cnt[i1], 1);
        g_rows[i1][p1] = 2 * t;     g_wt[i1][p1] = w1;
        int p2 = atomicAdd(&g_cnt[i2], 1);
        g_rows[i2][p2] = 2 * t + 1; g_wt[i2][p2] = w2;
    }
}

// =======================================================================
// up kernel (fused W1/W3): h = silu(xW1+b1)*(xW3+b3) -> g_H (fp32)
// TM=128, TN=64, TKC=16, DOUBLE-BUFFERED (one sync per chunk), 48KB smem
// warps 4(m) x 2(n); warp tile 32x32 (identical fragment code to R7)
// =======================================================================
__global__ __launch_bounds__(256, 2)
void up_kernel(const float* __restrict__ x,
               const float* __restrict__ W1, const float* __restrict__ b1,
               const float* __restrict__ W3, const float* __restrict__ b3) {
    int e = blockIdx.z;
    int cnt = g_cnt[e];
    int m0 = blockIdx.y * 128;
    if (m0 >= cnt) return;
    int n0 = blockIdx.x * 64;

    __shared__ __align__(16) uint32_t sAh[2][128*KW], sAl[2][128*KW];   // 24 KB
    __shared__ __align__(16) uint32_t sB1h[2][64*KW], sB1l[2][64*KW];   // 12 KB
    __shared__ __align__(16) uint32_t sB3h[2][64*KW], sB3l[2][64*KW];   // 12 KB

    int tid = threadIdx.x;
    int wid = tid >> 5;
    int lane = tid & 31;
    int grp = lane >> 2;
    int tig = lane & 3;
    int wm = (wid >> 1) * 32;      // 0,32,64,96
    int wn = (wid & 1) * 32;       // 0,32

    // A loader: rows arow and arow+64, aq float4 slot; tokens from g_rows directly
    int arow = tid >> 2, aq = tid & 3;
    int mA0 = m0 + arow, mA1 = mA0 + 64;
    int tok0 = (mA0 < cnt) ? (g_rows[e][mA0] >> 1) : -1;
    int tok1 = (mA1 < cnt) ? (g_rows[e][mA1] >> 1) : -1;
    const float* ap0 = x + (size_t)(tok0 < 0 ? 0 : tok0) * DIM + aq * 4;
    const float* ap1 = x + (size_t)(tok1 < 0 ? 0 : tok1) * DIM + aq * 4;

    // B loader: column bn (0..63), k-group bkg (0,4,8,12); [k][n] coalesced reads
    int bn = tid & 63, bkg = (tid >> 6) * 4;
    const float* W1e = W1 + (size_t)e * DIM * INTER + n0 + bn;
    const float* W3e = W3 + (size_t)e * DIM * INTER + n0 + bn;

    float4 rA0, rA1;
    float rB1[4], rB3[4];
    const float4 zf4 = make_float4(0.f, 0.f, 0.f, 0.f);

    auto fetch = [&](int c) {
        int k0 = c * TKC;
        rA0 = (tok0 >= 0) ? *reinterpret_cast<const float4*>(ap0 + k0) : zf4;
        rA1 = (tok1 >= 0) ? *reinterpret_cast<const float4*>(ap1 + k0) : zf4;
#pragma unroll
        for (int j = 0; j < 4; j++) {
            rB1[j] = W1e[(size_t)(k0 + bkg + j) * INTER];
            rB3[j] = W3e[(size_t)(k0 + bkg + j) * INTER];
        }
    };
    auto stage = [&](int buf) {
        uint32_t h0, l0, h1, l1;
        f2bf_pair(rA0.x, rA0.y, h0, l0);
        f2bf_pair(rA0.z, rA0.w, h1, l1);
        int ab0 = arow * KW + aq * 2;
        *reinterpret_cast<uint2*>(&sAh[buf][ab0]) = make_uint2(h0, h1);
        *reinterpret_cast<uint2*>(&sAl[buf][ab0]) = make_uint2(l0, l1);
        f2bf_pair(rA1.x, rA1.y, h0, l0);
        f2bf_pair(rA1.z, rA1.w, h1, l1);
        int ab1 = (arow + 64) * KW + aq * 2;
        *reinterpret_cast<uint2*>(&sAh[buf][ab1]) = make_uint2(h0, h1);
        *reinterpret_cast<uint2*>(&sAl[buf][ab1]) = make_uint2(l0, l1);

        int bb = bn * KW + (bkg >> 1);
        f2bf_pair(rB1[0], rB1[1], h0, l0);
        f2bf_pair(rB1[2], rB1[3], h1, l1);
        *reinterpret_cast<uint2*>(&sB1h[buf][bb]) = make_uint2(h0, h1);
        *reinterpret_cast<uint2*>(&sB1l[buf][bb]) = make_uint2(l0, l1);
        f2bf_pair(rB3[0], rB3[1], h0, l0);
        f2bf_pair(rB3[2], rB3[3], h1, l1);
        *reinterpret_cast<uint2*>(&sB3h[buf][bb]) = make_uint2(h0, h1);
        *reinterpret_cast<uint2*>(&sB3l[buf][bb]) = make_uint2(l0, l1);
    };

    float acc1[2][4][4], acc3[2][4][4];
#pragma unroll
    for (int mt = 0; mt < 2; mt++)
#pragma unroll
        for (int nt = 0; nt < 4; nt++)
#pragma unroll
            for (int j = 0; j < 4; j++) { acc1[mt][nt][j] = 0.f; acc3[mt][nt][j] = 0.f; }

    const int NC = DIM / TKC;   // 64
    fetch(0); stage(0);
    __syncthreads();
    fetch(1);

    for (int c = 0; c < NC; c++) {
        int cb = c & 1;
        if (c + 1 < NC) stage((c + 1) & 1);
        if (c + 2 < NC) fetch(c + 2);

        uint32_t ah[2][4], al[2][4];
#pragma unroll
        for (int mt = 0; mt < 2; mt++) {
            int r0 = (wm + mt * 16 + grp) * KW;
            int r1 = r0 + 8 * KW;
            ah[mt][0] = sAh[cb][r0 + tig];     ah[mt][1] = sAh[cb][r1 + tig];
            ah[mt][2] = sAh[cb][r0 + tig + 4]; ah[mt][3] = sAh[cb][r1 + tig + 4];
            al[mt][0] = sAl[cb][r0 + tig];     al[mt][1] = sAl[cb][r1 + tig];
            al[mt][2] = sAl[cb][r0 + tig + 4]; al[mt][3] = sAl[cb][r1 + tig + 4];
        }
#pragma unroll
        for (int nt = 0; nt < 4; nt++) {
            int nb = (wn + nt * 8 + grp) * KW;
            uint32_t b1h0 = sB1h[cb][nb + tig], b1h1 = sB1h[cb][nb + tig + 4];
            uint32_t b1l0 = sB1l[cb][nb + tig], b1l1 = sB1l[cb][nb + tig + 4];
            uint32_t b3h0 = sB3h[cb][nb + tig], b3h1 = sB3h[cb][nb + tig + 4];
            uint32_t b3l0 = sB3l[cb][nb + tig], b3l1 = sB3l[cb][nb + tig + 4];
#pragma unroll
            for (int mt = 0; mt < 2; mt++) {
                MMA16816(acc1[mt][nt], ah[mt], b1h0, b1h1);
                MMA16816(acc1[mt][nt], ah[mt], b1l0, b1l1);
                MMA16816(acc1[mt][nt], al[mt], b1h0, b1h1);
                MMA16816(acc3[mt][nt], ah[mt], b3h0, b3h1);
                MMA16816(acc3[mt][nt], ah[mt], b3l0, b3l1);
                MMA16816(acc3[mt][nt], al[mt], b3h0, b3h1);
            }
        }
        __syncthreads();
    }

    // epilogue: h = silu(z1+b1)*(z3+b3) -> g_H (fp32, R7-proven path)
    const float* pb1 = b1 + (size_t)e * INTER + n0;
    const float* pb3 = b3 + (size_t)e * INTER + n0;
#pragma unroll
    for (int mt = 0; mt < 2; mt++) {
#pragma unroll
        for (int half = 0; half < 2; half++) {
            int rloc = wm + mt * 16 + grp + half * 8;
            int m = m0 + rloc;
            if (m >= cnt) continue;
            int hr = g_rows[e][m];
            float* pH = g_H + (size_t)hr * INTER + n0;
#pragma unroll
            for (int nt = 0; nt < 4; nt++) {
                int col = wn + nt * 8 + tig * 2;
                float z1a = acc1[mt][nt][half * 2]     + pb1[col];
                float z1b = acc1[mt][nt][half * 2 + 1] + pb1[col + 1];
                float z3a = acc3[mt][nt][half * 2]     + pb3[col];
                float z3b = acc3[mt][nt][half * 2 + 1] + pb3[col + 1];
                float2 hv;
                hv.x = (z1a / (1.f + expf(-z1a))) * z3a;
                hv.y = (z1b / (1.f + expf(-z1b))) * z3b;
                *reinterpret_cast<float2*>(pH + col) = hv;
            }
        }
    }
}

// =======================================================================
// down GEMM: y[tok] += w * (gather(H) @ W2 + b2)
// TM=64, TN=128, TKC=16, DOUBLE-BUFFERED (R10 loop), fp32-H convert at stage
// =======================================================================
__global__ __launch_bounds__(256, 2)
void down_kernel(const float* __restrict__ W2, const float* __restrict__ b2,
                 float* __restrict__ y) {
    int e = blockIdx.z;
    int cnt = g_cnt[e];
    int m0 = blockIdx.y * 64;
    if (m0 >= cnt) return;
    int n0 = blockIdx.x * 128;

    __shared__ __align__(16) uint32_t sAh[2][64*KW], sAl[2][64*KW];
    __shared__ __align__(16) uint32_t sBh[2][128*KW], sBl[2][128*KW];
    __shared__ int   sHRow[64];
    __shared__ int   sTok[64];
    __shared__ float sW[64];

    int tid = threadIdx.x;
    int wid = tid >> 5;
    int lane = tid & 31;
    int grp = lane >> 2;
    int tig = lane & 3;
    int wm = (wid >> 2) * 32;
    int wn = (wid & 3) * 32;

    if (tid < 64) {
        int m = m0 + tid;
        if (m < cnt) {
            int r = g_rows[e][m];
            sHRow[tid] = r; sTok[tid] = r >> 1; sW[tid] = g_wt[e][m];
        } else { sHRow[tid] = -1; sTok[tid] = -1; sW[tid] = 0.f; }
    }
    __syncthreads();

    const float* W2e = W2 + (size_t)e * INTER * DIM + n0;   // [k][n]

    int arow = tid >> 2, aq = tid & 3;
    int myH = sHRow[arow];
    const float* aptr = (myH >= 0) ? (g_H + (size_t)myH * INTER + aq * 4) : g_H;
    int bn = tid & 127;
    int bkg = (tid >> 7) * 8;

    float4 rA;
    float rB[8];
    const float4 zf4 = make_float4(0.f, 0.f, 0.f, 0.f);

    auto fetch = [&](int c) {
        int k0 = c * TKC;
        rA = (myH >= 0) ? *reinterpret_cast<const float4*>(aptr + k0) : zf4;
#pragma unroll
        for (int j = 0; j < 8; j++)
            rB[j] = W2e[(size_t)(k0 + bkg + j) * DIM + bn];
    };
    auto stage = [&](int buf) {
        uint32_t h0, l0, h1, l1;
        f2bf_pair(rA.x, rA.y, h0, l0);
        f2bf_pair(rA.z, rA.w, h1, l1);
        int ab = arow * KW + aq * 2;
        *reinterpret_cast<uint2*>(&sAh[buf][ab]) = make_uint2(h0, h1);
        *reinterpret_cast<uint2*>(&sAl[buf][ab]) = make_uint2(l0, l1);
        int bb = bn * KW + (bkg >> 1);
        uint32_t bh[4], bl[4];
#pragma unroll
        for (int j = 0; j < 4; j++) f2bf_pair(rB[2*j], rB[2*j+1], bh[j], bl[j]);
        *reinterpret_cast<uint4*>(&sBh[buf][bb]) = make_uint4(bh[0], bh[1], bh[2], bh[3]);
        *reinterpret_cast<uint4*>(&sBl[buf][bb]) = make_uint4(bl[0], bl[1], bl[2], bl[3]);
    };

    float acc[2][4][4];
#pragma unroll
    for (int mt = 0; mt < 2; mt++)
#pragma unroll
        for (int nt = 0; nt < 4; nt++)
#pragma unroll
            for (int j = 0; j < 4; j++) acc[mt][nt][j] = 0.f;

    const int NC = INTER / TKC;   // 128
    fetch(0); stage(0);
    __syncthreads();
    fetch(1);

    for (int c = 0; c < NC; c++) {
        int cb = c & 1;
        if (c + 1 < NC) stage((c + 1) & 1);
        if (c + 2 < NC) fetch(c + 2);

        uint32_t ah[2][4], al[2][4];
#pragma unroll
        for (int mt = 0; mt < 2; mt++) {
            int r0 = (wm + mt * 16 + grp) * KW;
            int r1 = r0 + 8 * KW;
            ah[mt][0] = sAh[cb][r0 + tig];     ah[mt][1] = sAh[cb][r1 + tig];
            ah[mt][2] = sAh[cb][r0 + tig + 4]; ah[mt][3] = sAh[cb][r1 + tig + 4];
            al[mt][0] = sAl[cb][r0 + tig];     al[mt][1] = sAl[cb][r1 + tig];
            al[mt][2] = sAl[cb][r0 + tig + 4]; al[mt][3] = sAl[cb][r1 + tig + 4];
        }
#pragma unroll
        for (int nt = 0; nt < 4; nt++) {
            int nb = (wn + nt * 8 + grp) * KW;
            uint32_t bh0 = sBh[cb][nb + tig], bh1 = sBh[cb][nb + tig + 4];
            uint32_t bl0 = sBl[cb][nb + tig], bl1 = sBl[cb][nb + tig + 4];
#pragma unroll
            for (int mt = 0; mt < 2; mt++) {
                MMA16816(acc[mt][nt], ah[mt], bh0, bh1);
                MMA16816(acc[mt][nt], ah[mt], bl0, bl1);
                MMA16816(acc[mt][nt], al[mt], bh0, bh1);
            }
        }
        __syncthreads();
    }

    const float* pb2 = b2 + (size_t)e * DIM + n0;
#pragma unroll
    for (int mt = 0; mt < 2; mt++) {
#pragma unroll
        for (int half = 0; half < 2; half++) {
            int rloc = wm + mt * 16 + grp + half * 8;
            int tok = sTok[rloc];
            if (tok < 0) continue;
            float w = sW[rloc];
            float* yr = y + (size_t)tok * DIM + n0;
#pragma unroll
            for (int nt = 0; nt < 4; nt++) {
                int col = wn + nt * 8 + tig * 2;
                atomicAdd(yr + col,     (acc[mt][nt][half * 2]     + pb2[col])     * w);
                atomicAdd(yr + col + 1, (acc[mt][nt][half * 2 + 1] + pb2[col + 1]) * w);
            }
        }
    }
}

// -------------------------------- launcher --------------------------------------
extern "C" void kernel_launch(void* const* d_in, const int* in_sizes, int n_in,
                              void* d_out, int out_size) {
    const float* x  = (const float*)d_in[0];
    const float* Wg = (const float*)d_in[1];
    const float* bg = (const float*)d_in[2];
    const float* W1 = (const float*)d_in[3];
    const float* b1 = (const float*)d_in[4];
    const float* W2 = (const float*)d_in[5];
    const float* b2 = (const float*)d_in[6];
    const float* W3 = (const float*)d_in[7];
    const float* b3 = (const float*)d_in[8];
    float* y = (float*)d_out;

    zero_kernel<<<(T_TOK * DIM / 4 + 255) / 256, 256>>>(y);
    gate_kernel<<<T_TOK, 128>>>(x, Wg, bg);

    dim3 upGrid(INTER / 64, T_TOK / 128, NEXP);
    up_kernel<<<upGrid, 256>>>(x, W1, b1, W3, b3);

    dim3 dnGrid(DIM / 128, T_TOK / 64, NEXP);
    down_kernel<<<dnGrid, 256>>>(W2, b2, y);
}